// round 8
// baseline (speedup 1.0000x reference)
#include <cuda_runtime.h>
#include <cstdint>

#define HID    1024
#define INPD   512
#define BATCH  128
#define TSTEPS 256
#define G4H    4096
#define NB     128      // lstm persistent blocks
#define LT     256      // lstm threads

// ---- device-global scratch (no allocations allowed) ----
__device__ float    g_XS[134217728];          // [t][gate*1024+j][b] fp32 (512 MB)
__device__ uint32_t g_XT[512u * 32768u];      // x transposed+tf32: [i][t*128+b] (64 MB)
__device__ uint32_t g_WXp[4096u * 512u];      // Wx concat, tf32, fragment-permuted (8 MB)
__device__ float    g_H[2][HID * BATCH];      // h ping-pong (values pre-rounded to tf32)
__device__ unsigned g_bar;

__device__ __forceinline__ uint32_t f2tf(float f) {
    uint32_t u;
    asm("cvt.rna.tf32.f32 %0, %1;" : "=r"(u) : "f"(f));
    return u;
}
__device__ __forceinline__ void mma8(float* d, uint32_t a0, uint32_t a1, uint32_t a2,
                                     uint32_t a3, uint32_t b0, uint32_t b1) {
    asm volatile(
        "mma.sync.aligned.m16n8k8.row.col.f32.tf32.tf32.f32 "
        "{%0,%1,%2,%3}, {%4,%5,%6,%7}, {%8,%9}, {%0,%1,%2,%3};"
        : "+f"(d[0]), "+f"(d[1]), "+f"(d[2]), "+f"(d[3])
        : "r"(a0), "r"(a1), "r"(a2), "r"(a3), "r"(b0), "r"(b1));
}
__device__ __forceinline__ const float* sel4(const float* a, const float* b,
                                             const float* c, const float* d, int g) {
    return g == 0 ? a : (g == 1 ? b : (g == 2 ? c : d));
}
__device__ __forceinline__ float sigm(float x) { return 1.0f / (1.0f + expf(-x)); }

__device__ __forceinline__ void cp16(uint32_t dst, const void* src) {
    asm volatile("cp.async.cg.shared.global [%0], [%1], 16;" :: "r"(dst), "l"(src));
}
__device__ __forceinline__ void cpcommit() { asm volatile("cp.async.commit_group;"); }
template<int N> __device__ __forceinline__ void cpwait() {
    asm volatile("cp.async.wait_group %0;" :: "n"(N));
}

// ============================================================================
// prep_w: round Wx-concat to tf32 and store FRAGMENT-PERMUTED for xproj:
//   g_WXp[(((R>>4)*64 + k8)*32 + lane)*4 + j]  holds the exact m16n8k8 A-frag regs
// also resets the grid-barrier counter.
// ============================================================================
__global__ void prep_w_kernel(const float* __restrict__ Wg, const float* __restrict__ Wi,
                              const float* __restrict__ Wf, const float* __restrict__ Wo) {
    if (blockIdx.x == 0 && threadIdx.x == 0) g_bar = 0;
    int base = blockIdx.x * 256 + threadIdx.x;
#pragma unroll
    for (int i = 0; i < 4; ++i) {
        int o  = base + i * 524288;
        int j  = o & 3, ln = (o >> 2) & 31, k8 = (o >> 7) & 63, rb = o >> 13;
        int R  = rb * 16 + (ln >> 2) + (j & 1) * 8;
        int k  = k8 * 8 + (ln & 3) + ((j >> 1) & 1) * 4;
        const float* W = sel4(Wg, Wi, Wf, Wo, R >> 10);
        g_WXp[o] = f2tf(W[(size_t)(R & 1023) * INPD + k]);
    }
}

// ============================================================================
// prep_xt: transpose + tf32-round x:  g_XT[i][t*128+b] = tf32(x[b][t][i])
// ============================================================================
__global__ void prep_xt_kernel(const float* __restrict__ x) {
    __shared__ float tile[32][33];
    int tx = threadIdx.x & 31, ty = threadIdx.x >> 5;
    int it = blockIdx.x, nt = blockIdx.y;
#pragma unroll
    for (int r = 0; r < 4; ++r) {
        int n = nt * 32 + ty + r * 8;
        int t = n >> 7, b = n & 127;
        tile[ty + r * 8][tx] = x[(size_t)b * (TSTEPS * INPD) + t * INPD + it * 32 + tx];
    }
    __syncthreads();
#pragma unroll
    for (int r = 0; r < 4; ++r) {
        int il = ty + r * 8;
        g_XT[(size_t)(it * 32 + il) * 32768 + nt * 32 + tx] = f2tf(tile[tx][il]);
    }
}

// ============================================================================
// xproj: XS[t][R][b] = Wx[R]·x[b][t] + bias[R].  Tile M=128 x N=128(one t) x K=512.
// grid (32, 256), 256 threads (8 warps = 2M x 4N, warp tile 64x32).
// ============================================================================
__global__ void __launch_bounds__(256, 2) xproj_kernel(
    const float* __restrict__ bg, const float* __restrict__ bi,
    const float* __restrict__ bf, const float* __restrict__ bo) {
    extern __shared__ uint32_t sm[];
    uint32_t* sA = sm;                  // 2 bufs x 4096 u32  (frag layout)
    uint32_t* sB = sm + 8192;           // 2 bufs x 32 x 136 u32
    const uint32_t smem0 = (uint32_t)__cvta_generic_to_shared(sm);
    const int tid = threadIdx.x;
    const int m_base = blockIdx.x * 128;
    const int t = blockIdx.y;
    const int warp = tid >> 5, lane = tid & 31;
    const int wm = warp & 1, wn = warp >> 1;
    const int gid = lane >> 2, tig = lane & 3;

    float acc[4][4][4];
#pragma unroll
    for (int a = 0; a < 4; ++a)
#pragma unroll
        for (int b = 0; b < 4; ++b) {
            acc[a][b][0] = acc[a][b][1] = acc[a][b][2] = acc[a][b][3] = 0.f;
        }

    auto issue = [&](int kc, int buf) {
#pragma unroll
        for (int c = 0; c < 4; ++c) {                       // A: 16 KB frag-linear
            int u = c * 256 + tid;
            int rbl = u >> 7, q = u & 127;
            const uint32_t* src = g_WXp + (size_t)(((m_base >> 4) + rbl) * 64 + kc * 4) * 128 + q * 4;
            cp16(smem0 + (uint32_t)(buf * 4096 + rbl * 512 + q * 4) * 4, src);
        }
#pragma unroll
        for (int c = 0; c < 4; ++c) {                       // B: 32k x 128b
            int u = c * 256 + tid;
            int k = u >> 5, b4 = u & 31;
            const uint32_t* src = g_XT + (size_t)(kc * 32 + k) * 32768 + t * 128 + b4 * 4;
            cp16(smem0 + (uint32_t)(8192 + buf * 4352 + k * 136 + b4 * 4) * 4, src);
        }
    };
    issue(0, 0); cpcommit();
    issue(1, 1); cpcommit();

#pragma unroll 1
    for (int kc = 0; kc < 16; ++kc) {
        if (kc < 15) cpwait<1>(); else cpwait<0>();
        __syncthreads();
        const uint32_t* A = sA + (kc & 1) * 4096;
        const uint32_t* B = sB + (kc & 1) * 4352;
#pragma unroll
        for (int k8 = 0; k8 < 4; ++k8) {
            uint4 af[4];
#pragma unroll
            for (int mf = 0; mf < 4; ++mf)
                af[mf] = *(const uint4*)(A + (wm * 4 + mf) * 512 + k8 * 128 + lane * 4);
#pragma unroll
            for (int nf = 0; nf < 4; ++nf) {
                int n = wn * 32 + nf * 8 + gid;
                uint32_t b0 = B[(k8 * 8 + tig) * 136 + n];
                uint32_t b1 = B[(k8 * 8 + tig + 4) * 136 + n];
#pragma unroll
                for (int mf = 0; mf < 4; ++mf)
                    mma8(acc[mf][nf], af[mf].x, af[mf].y, af[mf].z, af[mf].w, b0, b1);
            }
        }
        __syncthreads();
        if (kc + 2 < 16) { issue(kc + 2, kc & 1); cpcommit(); }
    }

#pragma unroll
    for (int mf = 0; mf < 4; ++mf) {
        int R0 = m_base + wm * 64 + mf * 16 + gid;
        int R1 = R0 + 8;
        float bv0 = sel4(bg, bi, bf, bo, R0 >> 10)[R0 & 1023];
        float bv1 = sel4(bg, bi, bf, bo, R1 >> 10)[R1 & 1023];
#pragma unroll
        for (int nf = 0; nf < 4; ++nf) {
            int cc = wn * 32 + nf * 8 + tig * 2;
            float2 v0 = { acc[mf][nf][0] + bv0, acc[mf][nf][1] + bv0 };
            float2 v1 = { acc[mf][nf][2] + bv1, acc[mf][nf][3] + bv1 };
            *(float2*)&g_XS[((size_t)t * G4H + R0) * BATCH + cc] = v0;
            *(float2*)&g_XS[((size_t)t * G4H + R1) * BATCH + cc] = v1;
        }
    }
}

// ============================================================================
// lstm v3: 128 persistent blocks, 256 threads. Block owns 8 hidden units x 4
// gates (M=32), N=128 batch, K=1024.
//   - Wh tf32 frag-permuted resident in smem (128 KB), layout: one warp loads
//     its full M=32 A-frag as two conflict-free LDS.128 per k8.
//   - 2 compute warps (warp 0,1), warp tile 32x64: every B element read from
//     smem exactly once; A read twice. ~1.28 MB smem traffic/step (was 2.5).
//   - h staged via 3-buffer cp.async pipeline (KC=32), ONE __syncthreads per
//     chunk, issue-before-compute so 2 chunks are always in flight.
// smem: sW 131072 B | sB 3 x 17408 B (zs 32x136 f32 overlays buf0) = 183296 B.
// ============================================================================
#define LKC   32
#define BUFW  4352            // 32*136 u32 per buffer

__global__ void __launch_bounds__(LT, 1) lstm_kernel(
    const float* __restrict__ h0, const float* __restrict__ c0,
    const float* __restrict__ Wg, const float* __restrict__ Wi,
    const float* __restrict__ Wf, const float* __restrict__ Wo,
    float* __restrict__ out) {
    extern __shared__ uint32_t sm[];
    uint32_t* sW = sm;                  // 32768 u32
    uint32_t* sB = sm + 32768;          // 3 x 4352 u32
    float*    zs = (float*)(sm + 32768);
    const uint32_t smem0 = (uint32_t)__cvta_generic_to_shared(sm);
    const int tid = threadIdx.x;
    const int j0 = blockIdx.x * 8;
    const int warp = tid >> 5, lane = tid & 31;
    const int gid = lane >> 2, tig = lane & 3;
    const int wn = warp;                // compute warps: 0,1 -> N halves

    // prologue: fill frag-permuted Wh (tf32) once.
    // layout: sW[((k8g*2 + mf)*32 + lane)*4 + j], k8g in [0,128), mf in {0,1}
    // j=0:(gid,tig) j=1:(gid+8,tig) j=2:(gid,tig+4) j=3:(gid+8,tig+4); rows = mf*16+...
#pragma unroll 1
    for (int i = 0; i < 128; ++i) {
        int o   = i * LT + tid;
        int j   = o & 3, ln = (o >> 2) & 31, mf = (o >> 7) & 1, k8g = o >> 8;
        int row = mf * 16 + (ln >> 2) + (j & 1) * 8;    // row = gate*8 + u
        int k   = k8g * 8 + (ln & 3) + ((j >> 1) & 1) * 4;
        const float* W = sel4(Wg, Wi, Wf, Wo, row >> 3);
        sW[o] = f2tf(W[(size_t)(j0 + (row & 7)) * HID + k]);
    }
    // h0 rounded into g_H[1]; c state into registers (4 elems/thread)
    float creg[4];
#pragma unroll
    for (int e = 0; e < 4; ++e) {
        int idx = e * LT + tid, u = idx >> 7, b = idx & 127;
        g_H[1][(j0 + u) * BATCH + b] = __uint_as_float(f2tf(h0[(j0 + u) * BATCH + b]));
        creg[e] = c0[(j0 + u) * BATCH + b];
    }
    __syncthreads();
    if (tid == 0) { __threadfence(); atomicAdd(&g_bar, 1u); }

#pragma unroll 1
    for (int t = 0; t < TSTEPS; ++t) {
        // XS prefetch into registers (independent of grid barrier -> hides DRAM latency)
        float xsv[4][4];
        {
            const size_t xb = (size_t)t * (G4H * BATCH);
#pragma unroll
            for (int e = 0; e < 4; ++e) {
                int idx = e * LT + tid, u = idx >> 7, b = idx & 127;
#pragma unroll
                for (int g = 0; g < 4; ++g)
                    xsv[g][e] = g_XS[xb + (size_t)((g << 10) + j0 + u) * BATCH + b];
            }
        }
        // wait for h(t-1) from all blocks
        if (tid == 0) {
            const unsigned target = (unsigned)(t + 1) * NB;
            volatile unsigned* p = &g_bar;
            while (*p < target) { __nanosleep(32); }
            __threadfence();
        }
        __syncthreads();

        const float* hin = g_H[(t + 1) & 1];
        auto issueB = [&](int c, int buf) {
#pragma unroll
            for (int cc = 0; cc < 4; ++cc) {
                int u = cc * LT + tid;
                int kl = u >> 5, b4 = u & 31;
                cp16(smem0 + (uint32_t)(32768 + buf * BUFW + kl * 136 + b4 * 4) * 4,
                     hin + (c * LKC + kl) * BATCH + b4 * 4);
            }
        };
        issueB(0, 0); cpcommit();
        issueB(1, 1); cpcommit();

        float acc[2][8][4];
        if (warp < 2) {
#pragma unroll
            for (int mf = 0; mf < 2; ++mf)
#pragma unroll
                for (int nf = 0; nf < 8; ++nf) {
                    acc[mf][nf][0] = acc[mf][nf][1] = acc[mf][nf][2] = acc[mf][nf][3] = 0.f;
                }
        }
#pragma unroll 1
        for (int kc = 0; kc < 32; ++kc) {
            if (kc < 31) cpwait<1>(); else cpwait<0>();
            __syncthreads();
            if (kc + 2 < 32) { issueB(kc + 2, (kc + 2) % 3); cpcommit(); }
            if (warp < 2) {
                const uint32_t* B = sB + (kc % 3) * BUFW;
#pragma unroll
                for (int k8l = 0; k8l < 4; ++k8l) {
                    const int k8g = kc * 4 + k8l;
                    uint4 a0 = *(const uint4*)(sW + (k8g * 2) * 128 + lane * 4);
                    uint4 a1 = *(const uint4*)(sW + (k8g * 2 + 1) * 128 + lane * 4);
#pragma unroll
                    for (int nf = 0; nf < 8; ++nf) {
                        int n = wn * 64 + nf * 8 + gid;
                        uint32_t b0 = B[(k8l * 8 + tig) * 136 + n];
                        uint32_t b1 = B[(k8l * 8 + tig + 4) * 136 + n];
                        mma8(acc[0][nf], a0.x, a0.y, a0.z, a0.w, b0, b1);
                        mma8(acc[1][nf], a1.x, a1.y, a1.z, a1.w, b0, b1);
                    }
                }
            }
        }
        // stage z into smem (overlay on sB buf0; only warps 0-1 ever read sB)
        if (warp < 2) {
#pragma unroll
            for (int mf = 0; mf < 2; ++mf)
#pragma unroll
                for (int nf = 0; nf < 8; ++nf) {
                    int r = mf * 16 + gid;
                    int n = wn * 64 + nf * 8 + tig * 2;
                    zs[r * 136 + n]           = acc[mf][nf][0];
                    zs[r * 136 + n + 1]       = acc[mf][nf][1];
                    zs[(r + 8) * 136 + n]     = acc[mf][nf][2];
                    zs[(r + 8) * 136 + n + 1] = acc[mf][nf][3];
                }
        }
        __syncthreads();
        float* hw = g_H[t & 1];
#pragma unroll
        for (int e = 0; e < 4; ++e) {
            int idx = e * LT + tid, u = idx >> 7, b = idx & 127;
            float zg = zs[u * 136 + b]        + xsv[0][e];
            float zi = zs[(8 + u) * 136 + b]  + xsv[1][e];
            float zf = zs[(16 + u) * 136 + b] + xsv[2][e];
            float zo = zs[(24 + u) * 136 + b] + xsv[3][e];
            float cv = tanhf(zg) * sigm(zi) + creg[e] * sigm(zf);
            creg[e] = cv;
            float hv = tanhf(cv) * sigm(zo);
            hw[(j0 + u) * BATCH + b] = __uint_as_float(f2tf(hv));   // pre-rounded for next GEMM
            if (t == TSTEPS - 1) out[(j0 + u) * BATCH + b] = hv;
        }
        __syncthreads();
        if (tid == 0) { __threadfence(); atomicAdd(&g_bar, 1u); }
    }
}

// ============================================================================
extern "C" void kernel_launch(void* const* d_in, const int* in_sizes, int n_in,
                              void* d_out, int out_size) {
    const float* x   = (const float*)d_in[0];
    const float* c0  = (const float*)d_in[1];
    const float* h0  = (const float*)d_in[2];
    const float* Wgx = (const float*)d_in[3];
    const float* Wix = (const float*)d_in[4];
    const float* Wfx = (const float*)d_in[5];
    const float* Wox = (const float*)d_in[6];
    const float* Wgh = (const float*)d_in[7];
    const float* Wih = (const float*)d_in[8];
    const float* Wfh = (const float*)d_in[9];
    const float* Woh = (const float*)d_in[10];
    const float* bg  = (const float*)d_in[11];
    const float* bi  = (const float*)d_in[12];
    const float* bf  = (const float*)d_in[13];
    const float* bo  = (const float*)d_in[14];
    float* out = (float*)d_out;

    cudaFuncSetAttribute(xproj_kernel, cudaFuncAttributeMaxDynamicSharedMemorySize, 67584);
    cudaFuncSetAttribute(lstm_kernel,  cudaFuncAttributeMaxDynamicSharedMemorySize, 183296);

    prep_w_kernel<<<2048, 256>>>(Wgx, Wix, Wfx, Wox);
    prep_xt_kernel<<<dim3(16, 1024), 256>>>(x);
    xproj_kernel<<<dim3(32, 256), 256, 67584>>>(bg, bi, bf, bo);
    lstm_kernel<<<NB, LT, 183296>>>(h0, c0, Wgh, Wih, Wfh, Woh, out);
}

// round 10
// speedup vs baseline: 1.3138x; 1.3138x over previous
#include <cuda_runtime.h>
#include <cstdint>

#define HID    1024
#define INPD   512
#define BATCH  128
#define TSTEPS 256
#define G4H    4096
#define NB     128      // lstm persistent blocks
#define LT     256      // lstm threads

// ---- device-global scratch (no allocations allowed) ----
__device__ float    g_XS[134217728];          // [t][gate*1024+j][b] fp32 (512 MB)
__device__ uint32_t g_XT[512u * 32768u];      // x transposed+tf32: [i][t*128+b] (64 MB)
__device__ uint32_t g_WXp[4096u * 512u];      // Wx concat, tf32, fragment-permuted (8 MB)
__device__ float    g_H[2][HID * BATCH];      // h ping-pong (values pre-rounded to tf32)
__device__ unsigned g_bar;

__device__ __forceinline__ uint32_t f2tf(float f) {
    uint32_t u;
    asm("cvt.rna.tf32.f32 %0, %1;" : "=r"(u) : "f"(f));
    return u;
}
__device__ __forceinline__ void mma8(float* d, uint32_t a0, uint32_t a1, uint32_t a2,
                                     uint32_t a3, uint32_t b0, uint32_t b1) {
    asm volatile(
        "mma.sync.aligned.m16n8k8.row.col.f32.tf32.tf32.f32 "
        "{%0,%1,%2,%3}, {%4,%5,%6,%7}, {%8,%9}, {%0,%1,%2,%3};"
        : "+f"(d[0]), "+f"(d[1]), "+f"(d[2]), "+f"(d[3])
        : "r"(a0), "r"(a1), "r"(a2), "r"(a3), "r"(b0), "r"(b1));
}
__device__ __forceinline__ const float* sel4(const float* a, const float* b,
                                             const float* c, const float* d, int g) {
    return g == 0 ? a : (g == 1 ? b : (g == 2 ? c : d));
}
__device__ __forceinline__ float sigm(float x) { return 1.0f / (1.0f + expf(-x)); }

__device__ __forceinline__ void cp16(uint32_t dst, const void* src) {
    asm volatile("cp.async.cg.shared.global [%0], [%1], 16;" :: "r"(dst), "l"(src));
}
__device__ __forceinline__ void cpcommit() { asm volatile("cp.async.commit_group;"); }
template<int N> __device__ __forceinline__ void cpwait() {
    asm volatile("cp.async.wait_group %0;" :: "n"(N));
}

// ============================================================================
// prep_w: round Wx-concat to tf32 and store FRAGMENT-PERMUTED for xproj:
//   g_WXp[(((R>>4)*64 + k8)*32 + lane)*4 + j]  holds the exact m16n8k8 A-frag regs
// also resets the grid-barrier counter.
// ============================================================================
__global__ void prep_w_kernel(const float* __restrict__ Wg, const float* __restrict__ Wi,
                              const float* __restrict__ Wf, const float* __restrict__ Wo) {
    if (blockIdx.x == 0 && threadIdx.x == 0) g_bar = 0;
    int base = blockIdx.x * 256 + threadIdx.x;
#pragma unroll
    for (int i = 0; i < 4; ++i) {
        int o  = base + i * 524288;
        int j  = o & 3, ln = (o >> 2) & 31, k8 = (o >> 7) & 63, rb = o >> 13;
        int R  = rb * 16 + (ln >> 2) + (j & 1) * 8;
        int k  = k8 * 8 + (ln & 3) + ((j >> 1) & 1) * 4;
        const float* W = sel4(Wg, Wi, Wf, Wo, R >> 10);
        g_WXp[o] = f2tf(W[(size_t)(R & 1023) * INPD + k]);
    }
}

// ============================================================================
// prep_xt: transpose + tf32-round x:  g_XT[i][t*128+b] = tf32(x[b][t][i])
// ============================================================================
__global__ void prep_xt_kernel(const float* __restrict__ x) {
    __shared__ float tile[32][33];
    int tx = threadIdx.x & 31, ty = threadIdx.x >> 5;
    int it = blockIdx.x, nt = blockIdx.y;
#pragma unroll
    for (int r = 0; r < 4; ++r) {
        int n = nt * 32 + ty + r * 8;
        int t = n >> 7, b = n & 127;
        tile[ty + r * 8][tx] = x[(size_t)b * (TSTEPS * INPD) + t * INPD + it * 32 + tx];
    }
    __syncthreads();
#pragma unroll
    for (int r = 0; r < 4; ++r) {
        int il = ty + r * 8;
        g_XT[(size_t)(it * 32 + il) * 32768 + nt * 32 + tx] = f2tf(tile[tx][il]);
    }
}

// ============================================================================
// xproj: XS[t][R][b] = Wx[R]·x[b][t] + bias[R].  Tile M=128 x N=128(one t) x K=512.
// grid (32, 256), 256 threads (8 warps = 2M x 4N, warp tile 64x32).
// ============================================================================
__global__ void __launch_bounds__(256, 2) xproj_kernel(
    const float* __restrict__ bg, const float* __restrict__ bi,
    const float* __restrict__ bf, const float* __restrict__ bo) {
    extern __shared__ uint32_t sm[];
    uint32_t* sA = sm;                  // 2 bufs x 4096 u32  (frag layout)
    uint32_t* sB = sm + 8192;           // 2 bufs x 32 x 136 u32
    const uint32_t smem0 = (uint32_t)__cvta_generic_to_shared(sm);
    const int tid = threadIdx.x;
    const int m_base = blockIdx.x * 128;
    const int t = blockIdx.y;
    const int warp = tid >> 5, lane = tid & 31;
    const int wm = warp & 1, wn = warp >> 1;
    const int gid = lane >> 2, tig = lane & 3;

    float acc[4][4][4];
#pragma unroll
    for (int a = 0; a < 4; ++a)
#pragma unroll
        for (int b = 0; b < 4; ++b) {
            acc[a][b][0] = acc[a][b][1] = acc[a][b][2] = acc[a][b][3] = 0.f;
        }

    auto issue = [&](int kc, int buf) {
#pragma unroll
        for (int c = 0; c < 4; ++c) {                       // A: 16 KB frag-linear
            int u = c * 256 + tid;
            int rbl = u >> 7, q = u & 127;
            const uint32_t* src = g_WXp + (size_t)(((m_base >> 4) + rbl) * 64 + kc * 4) * 128 + q * 4;
            cp16(smem0 + (uint32_t)(buf * 4096 + rbl * 512 + q * 4) * 4, src);
        }
#pragma unroll
        for (int c = 0; c < 4; ++c) {                       // B: 32k x 128b
            int u = c * 256 + tid;
            int k = u >> 5, b4 = u & 31;
            const uint32_t* src = g_XT + (size_t)(kc * 32 + k) * 32768 + t * 128 + b4 * 4;
            cp16(smem0 + (uint32_t)(8192 + buf * 4352 + k * 136 + b4 * 4) * 4, src);
        }
    };
    issue(0, 0); cpcommit();
    issue(1, 1); cpcommit();

#pragma unroll 1
    for (int kc = 0; kc < 16; ++kc) {
        if (kc < 15) cpwait<1>(); else cpwait<0>();
        __syncthreads();
        const uint32_t* A = sA + (kc & 1) * 4096;
        const uint32_t* B = sB + (kc & 1) * 4352;
#pragma unroll
        for (int k8 = 0; k8 < 4; ++k8) {
            uint4 af[4];
#pragma unroll
            for (int mf = 0; mf < 4; ++mf)
                af[mf] = *(const uint4*)(A + (wm * 4 + mf) * 512 + k8 * 128 + lane * 4);
#pragma unroll
            for (int nf = 0; nf < 4; ++nf) {
                int n = wn * 32 + nf * 8 + gid;
                uint32_t b0 = B[(k8 * 8 + tig) * 136 + n];
                uint32_t b1 = B[(k8 * 8 + tig + 4) * 136 + n];
#pragma unroll
                for (int mf = 0; mf < 4; ++mf)
                    mma8(acc[mf][nf], af[mf].x, af[mf].y, af[mf].z, af[mf].w, b0, b1);
            }
        }
        __syncthreads();
        if (kc + 2 < 16) { issue(kc + 2, kc & 1); cpcommit(); }
    }

#pragma unroll
    for (int mf = 0; mf < 4; ++mf) {
        int R0 = m_base + wm * 64 + mf * 16 + gid;
        int R1 = R0 + 8;
        float bv0 = sel4(bg, bi, bf, bo, R0 >> 10)[R0 & 1023];
        float bv1 = sel4(bg, bi, bf, bo, R1 >> 10)[R1 & 1023];
#pragma unroll
        for (int nf = 0; nf < 4; ++nf) {
            int cc = wn * 32 + nf * 8 + tig * 2;
            float2 v0 = { acc[mf][nf][0] + bv0, acc[mf][nf][1] + bv0 };
            float2 v1 = { acc[mf][nf][2] + bv1, acc[mf][nf][3] + bv1 };
            *(float2*)&g_XS[((size_t)t * G4H + R0) * BATCH + cc] = v0;
            *(float2*)&g_XS[((size_t)t * G4H + R1) * BATCH + cc] = v1;
        }
    }
}

// ============================================================================
// lstm v4: 128 persistent blocks, 256 threads. Block owns 8 hidden units x 4
// gates (M=32), N=128 batch, K=1024.
//   - 4 COMPUTE WARPS (one per SMSP -> full tensor rate), warp tile 32x32:
//     B read from smem exactly once, A read 4x => ~1.5 MB smem/step.
//   - Wh tf32 frag-permuted resident in smem (128 KB) for the whole kernel.
//   - h staged via 4-buffer cp.async pipeline (KC=32), 3 chunks in flight,
//     always-commit tail keeps wait_group arithmetic exact.
// smem: sW 131072 B | sB 4 x 17408 B (zs 32x136 f32 overlays buf0) = 200704 B.
// ============================================================================
#define LKC   32
#define BUFW  4352            // 32*136 u32 per buffer

__global__ void __launch_bounds__(LT, 1) lstm_kernel(
    const float* __restrict__ h0, const float* __restrict__ c0,
    const float* __restrict__ Wg, const float* __restrict__ Wi,
    const float* __restrict__ Wf, const float* __restrict__ Wo,
    float* __restrict__ out) {
    extern __shared__ uint32_t sm[];
    uint32_t* sW = sm;                  // 32768 u32
    uint32_t* sB = sm + 32768;          // 4 x 4352 u32
    float*    zs = (float*)(sm + 32768);
    const uint32_t smem0 = (uint32_t)__cvta_generic_to_shared(sm);
    const int tid = threadIdx.x;
    const int j0 = blockIdx.x * 8;
    const int warp = tid >> 5, lane = tid & 31;
    const int gid = lane >> 2, tig = lane & 3;

    // prologue: fill frag-permuted Wh (tf32) once.
    // layout: sW[((k8g*2 + mf)*32 + lane)*4 + j], k8g in [0,128), mf in {0,1}
#pragma unroll 1
    for (int i = 0; i < 128; ++i) {
        int o   = i * LT + tid;
        int j   = o & 3, ln = (o >> 2) & 31, mf = (o >> 7) & 1, k8g = o >> 8;
        int row = mf * 16 + (ln >> 2) + (j & 1) * 8;    // row = gate*8 + u
        int k   = k8g * 8 + (ln & 3) + ((j >> 1) & 1) * 4;
        const float* W = sel4(Wg, Wi, Wf, Wo, row >> 3);
        sW[o] = f2tf(W[(size_t)(j0 + (row & 7)) * HID + k]);
    }
    // h0 rounded into g_H[1]; c state into registers (4 elems/thread)
    float creg[4];
#pragma unroll
    for (int e = 0; e < 4; ++e) {
        int idx = e * LT + tid, u = idx >> 7, b = idx & 127;
        g_H[1][(j0 + u) * BATCH + b] = __uint_as_float(f2tf(h0[(j0 + u) * BATCH + b]));
        creg[e] = c0[(j0 + u) * BATCH + b];
    }
    __syncthreads();
    if (tid == 0) { __threadfence(); atomicAdd(&g_bar, 1u); }

#pragma unroll 1
    for (int t = 0; t < TSTEPS; ++t) {
        // XS prefetch into registers (independent of grid barrier -> hides DRAM latency)
        float xsv[4][4];
        {
            const size_t xb = (size_t)t * (G4H * BATCH);
#pragma unroll
            for (int e = 0; e < 4; ++e) {
                int idx = e * LT + tid, u = idx >> 7, b = idx & 127;
#pragma unroll
                for (int g = 0; g < 4; ++g)
                    xsv[g][e] = g_XS[xb + (size_t)((g << 10) + j0 + u) * BATCH + b];
            }
        }
        // wait for h(t-1) from all blocks
        if (tid == 0) {
            const unsigned target = (unsigned)(t + 1) * NB;
            volatile unsigned* p = &g_bar;
            while (*p < target) { __nanosleep(32); }
            __threadfence();
        }
        __syncthreads();

        const float* hin = g_H[(t + 1) & 1];
        auto issueB = [&](int c, int buf) {
#pragma unroll
            for (int cc = 0; cc < 4; ++cc) {
                int u = cc * LT + tid;
                int kl = u >> 5, b4 = u & 31;
                cp16(smem0 + (uint32_t)(32768 + buf * BUFW + kl * 136 + b4 * 4) * 4,
                     hin + (c * LKC + kl) * BATCH + b4 * 4);
            }
        };
        issueB(0, 0); cpcommit();
        issueB(1, 1); cpcommit();
        issueB(2, 2); cpcommit();

        float acc[2][4][4];
        if (warp < 4) {
#pragma unroll
            for (int mf = 0; mf < 2; ++mf)
#pragma unroll
                for (int nf = 0; nf < 4; ++nf) {
                    acc[mf][nf][0] = acc[mf][nf][1] = acc[mf][nf][2] = acc[mf][nf][3] = 0.f;
                }
        }
#pragma unroll 1
        for (int kc = 0; kc < 32; ++kc) {
            cpwait<2>();
            __syncthreads();
            if (kc + 3 < 32) issueB(kc + 3, (kc + 3) & 3);
            cpcommit();                     // always commit: keeps group count exact
            if (warp < 4) {
                const uint32_t* B = sB + (kc & 3) * BUFW;
#pragma unroll
                for (int k8l = 0; k8l < 4; ++k8l) {
                    const int k8g = kc * 4 + k8l;
                    uint4 a0 = *(const uint4*)(sW + (k8g * 2) * 128 + lane * 4);
                    uint4 a1 = *(const uint4*)(sW + (k8g * 2 + 1) * 128 + lane * 4);
#pragma unroll
                    for (int nf = 0; nf < 4; ++nf) {
                        int n = warp * 32 + nf * 8 + gid;
                        uint32_t b0 = B[(k8l * 8 + tig) * 136 + n];
                        uint32_t b1 = B[(k8l * 8 + tig + 4) * 136 + n];
                        mma8(acc[0][nf], a0.x, a0.y, a0.z, a0.w, b0, b1);
                        mma8(acc[1][nf], a1.x, a1.y, a1.z, a1.w, b0, b1);
                    }
                }
            }
        }
        // stage z into smem (overlay on sB buf0; buf0's last chunk (28) long consumed)
        if (warp < 4) {
#pragma unroll
            for (int mf = 0; mf < 2; ++mf)
#pragma unroll
                for (int nf = 0; nf < 4; ++nf) {
                    int r = mf * 16 + gid;
                    int n = warp * 32 + nf * 8 + tig * 2;
                    zs[r * 136 + n]           = acc[mf][nf][0];
                    zs[r * 136 + n + 1]       = acc[mf][nf][1];
                    zs[(r + 8) * 136 + n]     = acc[mf][nf][2];
                    zs[(r + 8) * 136 + n + 1] = acc[mf][nf][3];
                }
        }
        __syncthreads();
        float* hw = g_H[t & 1];
#pragma unroll
        for (int e = 0; e < 4; ++e) {
            int idx = e * LT + tid, u = idx >> 7, b = idx & 127;
            float zg = zs[u * 136 + b]        + xsv[0][e];
            float zi = zs[(8 + u) * 136 + b]  + xsv[1][e];
            float zf = zs[(16 + u) * 136 + b] + xsv[2][e];
            float zo = zs[(24 + u) * 136 + b] + xsv[3][e];
            float cv = tanhf(zg) * sigm(zi) + creg[e] * sigm(zf);
            creg[e] = cv;
            float hv = tanhf(cv) * sigm(zo);
            hw[(j0 + u) * BATCH + b] = __uint_as_float(f2tf(hv));   // pre-rounded for next GEMM
            if (t == TSTEPS - 1) out[(j0 + u) * BATCH + b] = hv;
        }
        __syncthreads();
        if (tid == 0) { __threadfence(); atomicAdd(&g_bar, 1u); }
    }
}

// ============================================================================
extern "C" void kernel_launch(void* const* d_in, const int* in_sizes, int n_in,
                              void* d_out, int out_size) {
    const float* x   = (const float*)d_in[0];
    const float* c0  = (const float*)d_in[1];
    const float* h0  = (const float*)d_in[2];
    const float* Wgx = (const float*)d_in[3];
    const float* Wix = (const float*)d_in[4];
    const float* Wfx = (const float*)d_in[5];
    const float* Wox = (const float*)d_in[6];
    const float* Wgh = (const float*)d_in[7];
    const float* Wih = (const float*)d_in[8];
    const float* Wfh = (const float*)d_in[9];
    const float* Woh = (const float*)d_in[10];
    const float* bg  = (const float*)d_in[11];
    const float* bi  = (const float*)d_in[12];
    const float* bf  = (const float*)d_in[13];
    const float* bo  = (const float*)d_in[14];
    float* out = (float*)d_out;

    cudaFuncSetAttribute(xproj_kernel, cudaFuncAttributeMaxDynamicSharedMemorySize, 67584);
    cudaFuncSetAttribute(lstm_kernel,  cudaFuncAttributeMaxDynamicSharedMemorySize, 200704);

    prep_w_kernel<<<2048, 256>>>(Wgx, Wix, Wfx, Wox);
    prep_xt_kernel<<<dim3(16, 1024), 256>>>(x);
    xproj_kernel<<<dim3(32, 256), 256, 67584>>>(bg, bi, bf, bo);
    lstm_kernel<<<NB, LT, 200704>>>(h0, c0, Wgh, Wih, Wfh, Woh, out);
}

// round 11
// speedup vs baseline: 1.7221x; 1.3108x over previous
#include <cuda_runtime.h>
#include <cuda_fp16.h>
#include <cstdint>

#define HID    1024
#define INPD   512
#define BATCH  128
#define TSTEPS 256
#define G4H    4096
#define NB     128      // lstm persistent blocks
#define LT     256      // lstm threads

// ---- device-global scratch (no allocations allowed) ----
__device__ float    g_XS[134217728];          // [t][gate*1024+j][b] fp32 (512 MB)
__device__ uint32_t g_XT[512u * 32768u];      // x transposed+tf32: [i][t*128+b] (64 MB)
__device__ uint32_t g_WXp[4096u * 512u];      // Wx concat, tf32, fragment-permuted (8 MB)
__device__ uint32_t g_Hp[2][65536];           // h ping-pong, fp16 B-frag-permuted (256 KB x2)
__device__ unsigned g_bar;

__device__ __forceinline__ uint32_t f2tf(float f) {
    uint32_t u;
    asm("cvt.rna.tf32.f32 %0, %1;" : "=r"(u) : "f"(f));
    return u;
}
__device__ __forceinline__ void mma8(float* d, uint32_t a0, uint32_t a1, uint32_t a2,
                                     uint32_t a3, uint32_t b0, uint32_t b1) {
    asm volatile(
        "mma.sync.aligned.m16n8k8.row.col.f32.tf32.tf32.f32 "
        "{%0,%1,%2,%3}, {%4,%5,%6,%7}, {%8,%9}, {%0,%1,%2,%3};"
        : "+f"(d[0]), "+f"(d[1]), "+f"(d[2]), "+f"(d[3])
        : "r"(a0), "r"(a1), "r"(a2), "r"(a3), "r"(b0), "r"(b1));
}
// fp16 m16n8k16, fp32 accum
__device__ __forceinline__ void mma16(float* d, uint32_t a0, uint32_t a1, uint32_t a2,
                                      uint32_t a3, uint32_t b0, uint32_t b1) {
    asm volatile(
        "mma.sync.aligned.m16n8k16.row.col.f32.f16.f16.f32 "
        "{%0,%1,%2,%3}, {%4,%5,%6,%7}, {%8,%9}, {%0,%1,%2,%3};"
        : "+f"(d[0]), "+f"(d[1]), "+f"(d[2]), "+f"(d[3])
        : "r"(a0), "r"(a1), "r"(a2), "r"(a3), "r"(b0), "r"(b1));
}
__device__ __forceinline__ const float* sel4(const float* a, const float* b,
                                             const float* c, const float* d, int g) {
    return g == 0 ? a : (g == 1 ? b : (g == 2 ? c : d));
}
__device__ __forceinline__ float sigm(float x) { return 1.0f / (1.0f + expf(-x)); }
__device__ __forceinline__ uint32_t h2pack(float lo, float hi) {
    __half2 v = __floats2half2_rn(lo, hi);
    return *(uint32_t*)&v;
}

__device__ __forceinline__ void cp16(uint32_t dst, const void* src) {
    asm volatile("cp.async.cg.shared.global [%0], [%1], 16;" :: "r"(dst), "l"(src));
}
__device__ __forceinline__ void cpcommit() { asm volatile("cp.async.commit_group;"); }
template<int N> __device__ __forceinline__ void cpwait() {
    asm volatile("cp.async.wait_group %0;" :: "n"(N));
}

// h frag-permuted index: (j,b) -> ((j>>4)*16 + (b>>3))*64 + ((b&7)*4 + ((j&7)>>1))*2 + ((j&8)>>3)
// u32 holds halves (j even, j odd).

// ============================================================================
// prep_w: Wx concat -> tf32 fragment-permuted (for xproj). Resets g_bar.
// ============================================================================
__global__ void prep_w_kernel(const float* __restrict__ Wg, const float* __restrict__ Wi,
                              const float* __restrict__ Wf, const float* __restrict__ Wo) {
    if (blockIdx.x == 0 && threadIdx.x == 0) g_bar = 0;
    int base = blockIdx.x * 256 + threadIdx.x;
#pragma unroll
    for (int i = 0; i < 4; ++i) {
        int o  = base + i * 524288;
        int j  = o & 3, ln = (o >> 2) & 31, k8 = (o >> 7) & 63, rb = o >> 13;
        int R  = rb * 16 + (ln >> 2) + (j & 1) * 8;
        int k  = k8 * 8 + (ln & 3) + ((j >> 1) & 1) * 4;
        const float* W = sel4(Wg, Wi, Wf, Wo, R >> 10);
        g_WXp[o] = f2tf(W[(size_t)(R & 1023) * INPD + k]);
    }
}

// ============================================================================
// prep_h0: h0 fp32 [j][b] -> g_Hp[1] fp16 frag-permuted
// ============================================================================
__global__ void prep_h0_kernel(const float* __restrict__ h0) {
    int o = blockIdx.x * 256 + threadIdx.x;          // 65536 u32
    int reg = o & 1, lane = (o >> 1) & 31, n8 = (o >> 6) & 15, k16 = o >> 10;
    int p = lane & 3, gn = lane >> 2;
    int j = k16 * 16 + reg * 8 + 2 * p, b = n8 * 8 + gn;
    g_Hp[1][o] = h2pack(h0[j * BATCH + b], h0[(j + 1) * BATCH + b]);
}

// ============================================================================
// prep_xt: transpose + tf32-round x:  g_XT[i][t*128+b] = tf32(x[b][t][i])
// ============================================================================
__global__ void prep_xt_kernel(const float* __restrict__ x) {
    __shared__ float tile[32][33];
    int tx = threadIdx.x & 31, ty = threadIdx.x >> 5;
    int it = blockIdx.x, nt = blockIdx.y;
#pragma unroll
    for (int r = 0; r < 4; ++r) {
        int n = nt * 32 + ty + r * 8;
        int t = n >> 7, b = n & 127;
        tile[ty + r * 8][tx] = x[(size_t)b * (TSTEPS * INPD) + t * INPD + it * 32 + tx];
    }
    __syncthreads();
#pragma unroll
    for (int r = 0; r < 4; ++r) {
        int il = ty + r * 8;
        g_XT[(size_t)(it * 32 + il) * 32768 + nt * 32 + tx] = f2tf(tile[tx][il]);
    }
}

// ============================================================================
// xproj (unchanged, tf32): XS[t][R][b] = Wx[R]·x[b][t] + bias[R]
// ============================================================================
__global__ void __launch_bounds__(256, 2) xproj_kernel(
    const float* __restrict__ bg, const float* __restrict__ bi,
    const float* __restrict__ bf, const float* __restrict__ bo) {
    extern __shared__ uint32_t sm[];
    uint32_t* sA = sm;
    uint32_t* sB = sm + 8192;
    const uint32_t smem0 = (uint32_t)__cvta_generic_to_shared(sm);
    const int tid = threadIdx.x;
    const int m_base = blockIdx.x * 128;
    const int t = blockIdx.y;
    const int warp = tid >> 5, lane = tid & 31;
    const int wm = warp & 1, wn = warp >> 1;
    const int gid = lane >> 2, tig = lane & 3;

    float acc[4][4][4];
#pragma unroll
    for (int a = 0; a < 4; ++a)
#pragma unroll
        for (int b = 0; b < 4; ++b) {
            acc[a][b][0] = acc[a][b][1] = acc[a][b][2] = acc[a][b][3] = 0.f;
        }

    auto issue = [&](int kc, int buf) {
#pragma unroll
        for (int c = 0; c < 4; ++c) {
            int u = c * 256 + tid;
            int rbl = u >> 7, q = u & 127;
            const uint32_t* src = g_WXp + (size_t)(((m_base >> 4) + rbl) * 64 + kc * 4) * 128 + q * 4;
            cp16(smem0 + (uint32_t)(buf * 4096 + rbl * 512 + q * 4) * 4, src);
        }
#pragma unroll
        for (int c = 0; c < 4; ++c) {
            int u = c * 256 + tid;
            int k = u >> 5, b4 = u & 31;
            const uint32_t* src = g_XT + (size_t)(kc * 32 + k) * 32768 + t * 128 + b4 * 4;
            cp16(smem0 + (uint32_t)(8192 + buf * 4352 + k * 136 + b4 * 4) * 4, src);
        }
    };
    issue(0, 0); cpcommit();
    issue(1, 1); cpcommit();

#pragma unroll 1
    for (int kc = 0; kc < 16; ++kc) {
        if (kc < 15) cpwait<1>(); else cpwait<0>();
        __syncthreads();
        const uint32_t* A = sA + (kc & 1) * 4096;
        const uint32_t* B = sB + (kc & 1) * 4352;
#pragma unroll
        for (int k8 = 0; k8 < 4; ++k8) {
            uint4 af[4];
#pragma unroll
            for (int mf = 0; mf < 4; ++mf)
                af[mf] = *(const uint4*)(A + (wm * 4 + mf) * 512 + k8 * 128 + lane * 4);
#pragma unroll
            for (int nf = 0; nf < 4; ++nf) {
                int n = wn * 32 + nf * 8 + gid;
                uint32_t b0 = B[(k8 * 8 + tig) * 136 + n];
                uint32_t b1 = B[(k8 * 8 + tig + 4) * 136 + n];
#pragma unroll
                for (int mf = 0; mf < 4; ++mf)
                    mma8(acc[mf][nf], af[mf].x, af[mf].y, af[mf].z, af[mf].w, b0, b1);
            }
        }
        __syncthreads();
        if (kc + 2 < 16) { issue(kc + 2, kc & 1); cpcommit(); }
    }

#pragma unroll
    for (int mf = 0; mf < 4; ++mf) {
        int R0 = m_base + wm * 64 + mf * 16 + gid;
        int R1 = R0 + 8;
        float bv0 = sel4(bg, bi, bf, bo, R0 >> 10)[R0 & 1023];
        float bv1 = sel4(bg, bi, bf, bo, R1 >> 10)[R1 & 1023];
#pragma unroll
        for (int nf = 0; nf < 4; ++nf) {
            int cc = wn * 32 + nf * 8 + tig * 2;
            float2 v0 = { acc[mf][nf][0] + bv0, acc[mf][nf][1] + bv0 };
            float2 v1 = { acc[mf][nf][2] + bv1, acc[mf][nf][3] + bv1 };
            *(float2*)&g_XS[((size_t)t * G4H + R0) * BATCH + cc] = v0;
            *(float2*)&g_XS[((size_t)t * G4H + R1) * BATCH + cc] = v1;
        }
    }
}

// ============================================================================
// lstm v5 (fp16 recurrent GEMM): 128 persistent blocks, 256 threads.
// Block: M=32 rows (4 gates x 8 units) x N=128 batch x K=1024, m16n8k16 fp16.
//   - Wh fp16 A-frag-permuted resident in smem (64 KB).
//   - h in global as fp16 B-frag-permuted image -> per-chunk B is ONE
//     contiguous 8 KB cp.async; B-frag = single LDS.64.
//   - 4 compute warps (one per SMSP), warp tile 32x32; B read once.
//   - 4-buffer pipeline (chunk = 2 k16 = 8 KB), 3 in flight, always-commit.
// smem: sW 65536 | sB 32768 | zs 17408 | hsm 2048 = 117760 B.
// ============================================================================
#define SB_OFF   16384                  // u32 offset of sB
#define ZS_OFF   (16384 + 8192)        // u32 offset of zs
#define HS_OFF   (ZS_OFF + 4352)       // u32 offset of hsm

__global__ void __launch_bounds__(LT, 1) lstm_kernel(
    const float* __restrict__ c0,
    const float* __restrict__ Wg, const float* __restrict__ Wi,
    const float* __restrict__ Wf, const float* __restrict__ Wo,
    float* __restrict__ out) {
    extern __shared__ uint32_t sm[];
    uint32_t* sW  = sm;                          // 16384 u32 (fp16 A frags)
    uint32_t* sB  = sm + SB_OFF;                 // 4 x 2048 u32
    float*    zs  = (float*)(sm + ZS_OFF);       // 32 x 136 fp32
    __half*   hsm = (__half*)(sm + HS_OFF);      // 8 x 128 fp16
    const uint32_t smem0 = (uint32_t)__cvta_generic_to_shared(sm);
    const int tid = threadIdx.x;
    const int j0 = blockIdx.x * 8;
    const int warp = tid >> 5, lane = tid & 31;
    const int gid = lane >> 2, tig = lane & 3;
    const int hreg = (j0 >> 3) & 1;              // fixed frag reg for this block's j range
    const int hk16 = j0 >> 4;

    // prologue: Wh -> fp16 A-frag-permuted smem. 16384 u32.
    // sW[((k16*2+mt)*32+lane)*4+q]: q0:(gid, 2tig) q1:(gid+8, 2tig) q2:(gid, 2tig+8) q3:(gid+8, 2tig+8)
#pragma unroll 1
    for (int i = 0; i < 64; ++i) {
        int o    = i * LT + tid;
        int q    = o & 3, ln = (o >> 2) & 31, mt = (o >> 7) & 1, k16 = o >> 8;
        int row  = mt * 16 + (ln >> 2) + (q & 1) * 8;     // row = gate*8 + u
        int kk   = k16 * 16 + (ln & 3) * 2 + (q >> 1) * 8;
        const float* W = sel4(Wg, Wi, Wf, Wo, row >> 3);
        const float* wr = W + (size_t)(j0 + (row & 7)) * HID + kk;
        sW[o] = h2pack(wr[0], wr[1]);
    }
    // c state into registers (4 elems/thread)
    float creg[4];
#pragma unroll
    for (int e = 0; e < 4; ++e) {
        int idx = e * LT + tid, u = idx >> 7, b = idx & 127;
        creg[e] = c0[(j0 + u) * BATCH + b];
    }
    __syncthreads();
    if (tid == 0) { __threadfence(); atomicAdd(&g_bar, 1u); }

#pragma unroll 1
    for (int t = 0; t < TSTEPS; ++t) {
        // XS prefetch (independent of barrier -> hides DRAM latency under spin)
        float xsv[4][4];
        {
            const size_t xb = (size_t)t * (G4H * BATCH);
#pragma unroll
            for (int e = 0; e < 4; ++e) {
                int idx = e * LT + tid, u = idx >> 7, b = idx & 127;
#pragma unroll
                for (int g = 0; g < 4; ++g)
                    xsv[g][e] = g_XS[xb + (size_t)((g << 10) + j0 + u) * BATCH + b];
            }
        }
        // wait for h(t-1) from all blocks
        if (tid == 0) {
            const unsigned target = (unsigned)(t + 1) * NB;
            volatile unsigned* p = &g_bar;
            while (*p < target) { __nanosleep(32); }
            __threadfence();
        }
        __syncthreads();

        const uint32_t* hin = g_Hp[(t + 1) & 1];
        auto issueB = [&](int c, int buf) {          // chunk = 2 k16 = 2048 u32, contiguous
#pragma unroll
            for (int cc = 0; cc < 2; ++cc) {
                int u = cc * LT + tid;               // u in [0,512)
                cp16(smem0 + (uint32_t)(SB_OFF + buf * 2048 + u * 4) * 4,
                     hin + c * 2048 + u * 4);
            }
        };
        issueB(0, 0); cpcommit();
        issueB(1, 1); cpcommit();
        issueB(2, 2); cpcommit();

        float acc[2][4][4];
#pragma unroll
        for (int mt = 0; mt < 2; ++mt)
#pragma unroll
            for (int nf = 0; nf < 4; ++nf) {
                acc[mt][nf][0] = acc[mt][nf][1] = acc[mt][nf][2] = acc[mt][nf][3] = 0.f;
            }
#pragma unroll 1
        for (int kc = 0; kc < 32; ++kc) {
            cpwait<2>();
            __syncthreads();
            if (kc + 3 < 32) issueB(kc + 3, (kc + 3) & 3);
            cpcommit();                               // always commit: group count exact
            if (warp < 4) {
                const uint32_t* B = sB + (kc & 3) * 2048;
#pragma unroll
                for (int k16l = 0; k16l < 2; ++k16l) {
                    const int k16 = kc * 2 + k16l;
                    uint4 a0 = *(const uint4*)(sW + ((k16 * 2) * 32 + lane) * 4);
                    uint4 a1 = *(const uint4*)(sW + ((k16 * 2 + 1) * 32 + lane) * 4);
#pragma unroll
                    for (int nf = 0; nf < 4; ++nf) {
                        const int n8 = warp * 4 + nf;
                        uint2 b01 = *(const uint2*)(B + (k16l * 16 + n8) * 64 + lane * 2);
                        mma16(acc[0][nf], a0.x, a0.y, a0.z, a0.w, b01.x, b01.y);
                        mma16(acc[1][nf], a1.x, a1.y, a1.z, a1.w, b01.x, b01.y);
                    }
                }
            }
        }
        // stage z into smem
        if (warp < 4) {
#pragma unroll
            for (int mt = 0; mt < 2; ++mt)
#pragma unroll
                for (int nf = 0; nf < 4; ++nf) {
                    int r = mt * 16 + gid;
                    int n = warp * 32 + nf * 8 + tig * 2;
                    zs[r * 136 + n]           = acc[mt][nf][0];
                    zs[r * 136 + n + 1]       = acc[mt][nf][1];
                    zs[(r + 8) * 136 + n]     = acc[mt][nf][2];
                    zs[(r + 8) * 136 + n + 1] = acc[mt][nf][3];
                }
        }
        __syncthreads();
        // elementwise epilogue: c update, h = tanh(c)*sigm(zo); stage h fp16
#pragma unroll
        for (int e = 0; e < 4; ++e) {
            int idx = e * LT + tid, u = idx >> 7, b = idx & 127;
            float zg = zs[u * 136 + b]        + xsv[0][e];
            float zi = zs[(8 + u) * 136 + b]  + xsv[1][e];
            float zf = zs[(16 + u) * 136 + b] + xsv[2][e];
            float zo = zs[(24 + u) * 136 + b] + xsv[3][e];
            float cv = tanhf(zg) * sigm(zi) + creg[e] * sigm(zf);
            creg[e] = cv;
            float hv = tanhf(cv) * sigm(zo);
            hsm[u * 128 + b] = __float2half_rn(hv);
            if (t == TSTEPS - 1) out[(j0 + u) * BATCH + b] = hv;
        }
        __syncthreads();
        // write block's h slice to global fp16 B-frag-permuted image (512 u32)
        {
            uint32_t* hw = g_Hp[t & 1];
#pragma unroll
            for (int w2 = 0; w2 < 2; ++w2) {
                int w = w2 * LT + tid;               // [0,512)
                int ln = w & 31, n8 = w >> 5;
                int p = ln & 3, gn = ln >> 2;
                int u = 2 * p, b = n8 * 8 + gn;
                uint32_t v = ((uint32_t)*(const uint16_t*)&hsm[u * 128 + b]) |
                             ((uint32_t)*(const uint16_t*)&hsm[(u + 1) * 128 + b] << 16);
                hw[(hk16 * 16 + n8) * 64 + ln * 2 + hreg] = v;
            }
        }
        __syncthreads();
        if (tid == 0) { __threadfence(); atomicAdd(&g_bar, 1u); }
    }
}

// ============================================================================
extern "C" void kernel_launch(void* const* d_in, const int* in_sizes, int n_in,
                              void* d_out, int out_size) {
    const float* x   = (const float*)d_in[0];
    const float* c0  = (const float*)d_in[1];
    const float* h0  = (const float*)d_in[2];
    const float* Wgx = (const float*)d_in[3];
    const float* Wix = (const float*)d_in[4];
    const float* Wfx = (const float*)d_in[5];
    const float* Wox = (const float*)d_in[6];
    const float* Wgh = (const float*)d_in[7];
    const float* Wih = (const float*)d_in[8];
    const float* Wfh = (const float*)d_in[9];
    const float* Woh = (const float*)d_in[10];
    const float* bg  = (const float*)d_in[11];
    const float* bi  = (const float*)d_in[12];
    const float* bf  = (const float*)d_in[13];
    const float* bo  = (const float*)d_in[14];
    float* out = (float*)d_out;

    cudaFuncSetAttribute(xproj_kernel, cudaFuncAttributeMaxDynamicSharedMemorySize, 67584);
    cudaFuncSetAttribute(lstm_kernel,  cudaFuncAttributeMaxDynamicSharedMemorySize, 117760);

    prep_w_kernel<<<2048, 256>>>(Wgx, Wix, Wfx, Wox);
    prep_h0_kernel<<<256, 256>>>(h0);
    prep_xt_kernel<<<dim3(16, 1024), 256>>>(x);
    xproj_kernel<<<dim3(32, 256), 256, 67584>>>(bg, bi, bf, bo);
    lstm_kernel<<<NB, LT, 117760>>>(c0, Wgh, Wih, Wfh, Woh, out);
}

// round 12
// speedup vs baseline: 1.8046x; 1.0479x over previous
#include <cuda_runtime.h>
#include <cuda_fp16.h>
#include <cstdint>

#define HID    1024
#define INPD   512
#define BATCH  128
#define TSTEPS 256
#define G4H    4096
#define NB     128      // lstm persistent blocks
#define LT     256      // lstm threads

// ---- device-global scratch (no allocations allowed) ----
__device__ float    g_XS[134217728];          // [t][gate*1024+j][b] fp32 (512 MB)
__device__ uint32_t g_XTh[8388608];           // x fp16 B-frag image: [t][k16][n8][ln*2+reg] (32 MB)
__device__ uint32_t g_WXh[1048576];           // Wx fp16 A-frag image: [mt][k16][ln*4+q] (4 MB)
__device__ uint32_t g_Hp[2][65536];           // h ping-pong, fp16 B-frag-permuted (256 KB x2)
__device__ unsigned g_bar;

// fp16 m16n8k16, fp32 accum
__device__ __forceinline__ void mma16(float* d, uint32_t a0, uint32_t a1, uint32_t a2,
                                      uint32_t a3, uint32_t b0, uint32_t b1) {
    asm volatile(
        "mma.sync.aligned.m16n8k16.row.col.f32.f16.f16.f32 "
        "{%0,%1,%2,%3}, {%4,%5,%6,%7}, {%8,%9}, {%0,%1,%2,%3};"
        : "+f"(d[0]), "+f"(d[1]), "+f"(d[2]), "+f"(d[3])
        : "r"(a0), "r"(a1), "r"(a2), "r"(a3), "r"(b0), "r"(b1));
}
__device__ __forceinline__ const float* sel4(const float* a, const float* b,
                                             const float* c, const float* d, int g) {
    return g == 0 ? a : (g == 1 ? b : (g == 2 ? c : d));
}
__device__ __forceinline__ float sigm(float x) { return 1.0f / (1.0f + expf(-x)); }
__device__ __forceinline__ uint32_t h2pack(float lo, float hi) {
    __half2 v = __floats2half2_rn(lo, hi);
    return *(uint32_t*)&v;
}
__device__ __forceinline__ void cp16(uint32_t dst, const void* src) {
    asm volatile("cp.async.cg.shared.global [%0], [%1], 16;" :: "r"(dst), "l"(src));
}
__device__ __forceinline__ void cpcommit() { asm volatile("cp.async.commit_group;"); }
template<int N> __device__ __forceinline__ void cpwait() {
    asm volatile("cp.async.wait_group %0;" :: "n"(N));
}

// ============================================================================
// prep_w: Wx concat -> fp16 A-frag image g_WXh[mt][k16][ln*4+q]. Resets g_bar.
//   q0:(gid,2tig) q1:(gid+8,2tig) q2:(gid,2tig+8) q3:(gid+8,2tig+8); u32=(k,k+1)
// ============================================================================
__global__ void prep_w_kernel(const float* __restrict__ Wg, const float* __restrict__ Wi,
                              const float* __restrict__ Wf, const float* __restrict__ Wo) {
    if (blockIdx.x == 0 && threadIdx.x == 0) g_bar = 0;
    int base = blockIdx.x * 256 + threadIdx.x;
#pragma unroll
    for (int i = 0; i < 4; ++i) {
        int o   = base + i * 262144;
        int q   = o & 3, ln = (o >> 2) & 31, k16 = (o >> 7) & 31, mt = o >> 12;
        int R   = mt * 16 + (ln >> 2) + (q & 1) * 8;
        int k   = k16 * 16 + (ln & 3) * 2 + (q >> 1) * 8;
        const float* W = sel4(Wg, Wi, Wf, Wo, R >> 10);
        const float* wr = W + (size_t)(R & 1023) * INPD + k;
        g_WXh[o] = h2pack(wr[0], wr[1]);
    }
}

// ============================================================================
// prep_h0: h0 fp32 [j][b] -> g_Hp[1] fp16 frag-permuted
// ============================================================================
__global__ void prep_h0_kernel(const float* __restrict__ h0) {
    int o = blockIdx.x * 256 + threadIdx.x;          // 65536 u32
    int reg = o & 1, lane = (o >> 1) & 31, n8 = (o >> 6) & 15, k16 = o >> 10;
    int p = lane & 3, gn = lane >> 2;
    int j = k16 * 16 + reg * 8 + 2 * p, b = n8 * 8 + gn;
    g_Hp[1][o] = h2pack(h0[j * BATCH + b], h0[(j + 1) * BATCH + b]);
}

// ============================================================================
// prep_xt: x -> fp16 B-frag image g_XTh[((t*32+k16)*16+n8)*64 + ln*2 + reg]
//   u32 = (x[b][t][i], x[b][t][i+1]), i = k16*16+reg*8+2p, b = n8*8+gn
// ============================================================================
__global__ void prep_xt_kernel(const float* __restrict__ x) {
    int o = blockIdx.x * 1024 + threadIdx.x;
#pragma unroll
    for (int i = 0; i < 4; ++i, o += 256) {
        int reg = o & 1, ln = (o >> 1) & 31, n8 = (o >> 6) & 15, k16 = (o >> 10) & 31, t = o >> 15;
        int p = ln & 3, gn = ln >> 2;
        int ii = k16 * 16 + reg * 8 + 2 * p, b = n8 * 8 + gn;
        const float* xr = x + (size_t)b * (TSTEPS * INPD) + (size_t)t * INPD + ii;
        g_XTh[o] = h2pack(xr[0], xr[1]);
    }
}

// ============================================================================
// xproj (fp16 m16n8k16): XS[t][R][b] = Wx[R]·x[b][t] + bias[R]
// grid (32, 256), 256 threads (8 warps = 2M x 4N, warp tile 64x32).
// Chunk KC=64 (4 k16), double-buffered: smem 2x(4096+4096) u32 = 64 KB.
// ============================================================================
__global__ void __launch_bounds__(256, 2) xproj_kernel(
    const float* __restrict__ bg, const float* __restrict__ bi,
    const float* __restrict__ bf, const float* __restrict__ bo) {
    extern __shared__ uint32_t sm[];
    const uint32_t smem0 = (uint32_t)__cvta_generic_to_shared(sm);
    const int tid = threadIdx.x;
    const int m_base = blockIdx.x * 128;
    const int mt0 = m_base >> 4;
    const int t = blockIdx.y;
    const int warp = tid >> 5, lane = tid & 31;
    const int wm = warp & 1, wn = warp >> 1;
    const int gid = lane >> 2, tig = lane & 3;

    float acc[4][4][4];
#pragma unroll
    for (int a = 0; a < 4; ++a)
#pragma unroll
        for (int b = 0; b < 4; ++b) {
            acc[a][b][0] = acc[a][b][1] = acc[a][b][2] = acc[a][b][3] = 0.f;
        }

    auto issue = [&](int kc, int buf) {
#pragma unroll
        for (int c = 0; c < 4; ++c) {                       // A: 4096 u32
            int u = c * 256 + tid;
            int idx = u >> 5, lq = u & 31;                  // idx = k16l*8 + mtl
            int k16l = idx >> 3, mtl = idx & 7;
            const uint32_t* src = g_WXh + ((size_t)(mt0 + mtl) * 32 + kc * 4 + k16l) * 128 + lq * 4;
            cp16(smem0 + (uint32_t)(buf * 4096 + idx * 128 + lq * 4) * 4, src);
        }
#pragma unroll
        for (int c = 0; c < 4; ++c) {                       // B: 4096 u32
            int u = c * 256 + tid;
            int idx = u >> 4, q16 = u & 15;                 // idx = k16l*16 + n8
            const uint32_t* src = g_XTh + ((size_t)(t * 32 + kc * 4) * 16 + idx) * 64 + q16 * 4;
            cp16(smem0 + (uint32_t)(8192 + buf * 4096 + idx * 64 + q16 * 4) * 4, src);
        }
    };
    issue(0, 0); cpcommit();
    issue(1, 1); cpcommit();

#pragma unroll 1
    for (int kc = 0; kc < 8; ++kc) {
        if (kc < 7) cpwait<1>(); else cpwait<0>();
        __syncthreads();
        const uint32_t* A = sm + (kc & 1) * 4096;
        const uint32_t* B = sm + 8192 + (kc & 1) * 4096;
#pragma unroll
        for (int k16l = 0; k16l < 4; ++k16l) {
            uint4 af[4];
#pragma unroll
            for (int mf = 0; mf < 4; ++mf)
                af[mf] = *(const uint4*)(A + ((k16l * 8 + wm * 4 + mf) * 32 + lane) * 4);
#pragma unroll
            for (int nf = 0; nf < 4; ++nf) {
                int n8 = wn * 4 + nf;
                uint2 b01 = *(const uint2*)(B + (k16l * 16 + n8) * 64 + lane * 2);
#pragma unroll
                for (int mf = 0; mf < 4; ++mf)
                    mma16(acc[mf][nf], af[mf].x, af[mf].y, af[mf].z, af[mf].w, b01.x, b01.y);
            }
        }
        __syncthreads();
        if (kc + 2 < 8) { issue(kc + 2, kc & 1); cpcommit(); }
    }

#pragma unroll
    for (int mf = 0; mf < 4; ++mf) {
        int R0 = m_base + wm * 64 + mf * 16 + gid;
        int R1 = R0 + 8;
        float bv0 = sel4(bg, bi, bf, bo, R0 >> 10)[R0 & 1023];
        float bv1 = sel4(bg, bi, bf, bo, R1 >> 10)[R1 & 1023];
#pragma unroll
        for (int nf = 0; nf < 4; ++nf) {
            int cc = wn * 32 + nf * 8 + tig * 2;
            float2 v0 = { acc[mf][nf][0] + bv0, acc[mf][nf][1] + bv0 };
            float2 v1 = { acc[mf][nf][2] + bv1, acc[mf][nf][3] + bv1 };
            *(float2*)&g_XS[((size_t)t * G4H + R0) * BATCH + cc] = v0;
            *(float2*)&g_XS[((size_t)t * G4H + R1) * BATCH + cc] = v1;
        }
    }
}

// ============================================================================
// lstm v6: register-resident epilogue. 128 persistent blocks, 256 threads.
// M=32 (4 gates x 8 units) x N=128 x K=1024, fp16 m16n8k16.
//   - acc of thread (warp,gid,tig) holds ALL 4 gates of unit u=gid at cols
//     n=warp*32+nf*8+tig*2+{0,1}: zg=acc[0][nf][c], zi=acc[0][nf][2+c],
//     zf=acc[1][nf][c], zo=acc[1][nf][2+c]. Gate math fully in registers.
//   - h packed to global frag image directly via shfl.xor(4) (partner unit).
//   - no zs/hsm staging; smem = sW 64 KB + sB 32 KB = 96 KB.
// ============================================================================
#define SB_OFF   16384                  // u32 offset of sB

__global__ void __launch_bounds__(LT, 1) lstm_kernel(
    const float* __restrict__ c0,
    const float* __restrict__ Wg, const float* __restrict__ Wi,
    const float* __restrict__ Wf, const float* __restrict__ Wo,
    float* __restrict__ out) {
    extern __shared__ uint32_t sm[];
    uint32_t* sW  = sm;                          // 16384 u32 (fp16 A frags)
    uint32_t* sB  = sm + SB_OFF;                 // 4 x 2048 u32
    const uint32_t smem0 = (uint32_t)__cvta_generic_to_shared(sm);
    const int tid = threadIdx.x;
    const int j0 = blockIdx.x * 8;
    const int warp = tid >> 5, lane = tid & 31;
    const int gid = lane >> 2, tig = lane & 3;
    const int hreg = (j0 >> 3) & 1;
    const int hk16 = j0 >> 4;
    const bool cw = (warp < 4);

    // prologue: Wh -> fp16 A-frag-permuted smem (16384 u32)
#pragma unroll 1
    for (int i = 0; i < 64; ++i) {
        int o    = i * LT + tid;
        int q    = o & 3, ln = (o >> 2) & 31, mt = (o >> 7) & 1, k16 = o >> 8;
        int row  = mt * 16 + (ln >> 2) + (q & 1) * 8;
        int kk   = k16 * 16 + (ln & 3) * 2 + (q >> 1) * 8;
        const float* W = sel4(Wg, Wi, Wf, Wo, row >> 3);
        const float* wr = W + (size_t)(j0 + (row & 7)) * HID + kk;
        sW[o] = h2pack(wr[0], wr[1]);
    }
    // c state in acc layout: creg[nf*2+c] = c(u=gid, n=warp*32+nf*8+tig*2+c)
    float creg[8];
    if (cw) {
#pragma unroll
        for (int nf = 0; nf < 4; ++nf)
#pragma unroll
            for (int c = 0; c < 2; ++c)
                creg[nf * 2 + c] = c0[(j0 + gid) * BATCH + warp * 32 + nf * 8 + tig * 2 + c];
    }
    __syncthreads();
    if (tid == 0) { __threadfence(); atomicAdd(&g_bar, 1u); }

#pragma unroll 1
    for (int t = 0; t < TSTEPS; ++t) {
        // XS prefetch into registers (independent of barrier -> hides latency)
        float xsv[4][8];
        if (cw) {
            const size_t xb = (size_t)t * (G4H * BATCH);
            const int nb = warp * 32 + tig * 2;
#pragma unroll
            for (int g = 0; g < 4; ++g) {
                const float* p = &g_XS[xb + (size_t)((g << 10) + j0 + gid) * BATCH + nb];
#pragma unroll
                for (int nf = 0; nf < 4; ++nf) {
                    xsv[g][nf * 2]     = p[nf * 8];
                    xsv[g][nf * 2 + 1] = p[nf * 8 + 1];
                }
            }
        }
        // wait for h(t-1) from all blocks
        if (tid == 0) {
            const unsigned target = (unsigned)(t + 1) * NB;
            volatile unsigned* p = &g_bar;
            while (*p < target) { __nanosleep(32); }
            __threadfence();
        }
        __syncthreads();

        const uint32_t* hin = g_Hp[(t + 1) & 1];
        auto issueB = [&](int c, int buf) {          // chunk = 2 k16 = 2048 u32
#pragma unroll
            for (int cc = 0; cc < 2; ++cc) {
                int u = cc * LT + tid;
                cp16(smem0 + (uint32_t)(SB_OFF + buf * 2048 + u * 4) * 4,
                     hin + c * 2048 + u * 4);
            }
        };
        issueB(0, 0); cpcommit();
        issueB(1, 1); cpcommit();
        issueB(2, 2); cpcommit();

        float acc[2][4][4];
#pragma unroll
        for (int mt = 0; mt < 2; ++mt)
#pragma unroll
            for (int nf = 0; nf < 4; ++nf) {
                acc[mt][nf][0] = acc[mt][nf][1] = acc[mt][nf][2] = acc[mt][nf][3] = 0.f;
            }
#pragma unroll 1
        for (int kc = 0; kc < 32; ++kc) {
            cpwait<2>();
            __syncthreads();
            if (kc + 3 < 32) issueB(kc + 3, (kc + 3) & 3);
            cpcommit();                               // always commit: group count exact
            if (cw) {
                const uint32_t* B = sB + (kc & 3) * 2048;
#pragma unroll
                for (int k16l = 0; k16l < 2; ++k16l) {
                    const int k16 = kc * 2 + k16l;
                    uint4 a0 = *(const uint4*)(sW + ((k16 * 2) * 32 + lane) * 4);
                    uint4 a1 = *(const uint4*)(sW + ((k16 * 2 + 1) * 32 + lane) * 4);
#pragma unroll
                    for (int nf = 0; nf < 4; ++nf) {
                        const int n8 = warp * 4 + nf;
                        uint2 b01 = *(const uint2*)(B + (k16l * 16 + n8) * 64 + lane * 2);
                        mma16(acc[0][nf], a0.x, a0.y, a0.z, a0.w, b01.x, b01.y);
                        mma16(acc[1][nf], a1.x, a1.y, a1.z, a1.w, b01.x, b01.y);
                    }
                }
            }
        }
        // register epilogue + direct h frag write
        if (cw) {
            float hv[8];
#pragma unroll
            for (int nf = 0; nf < 4; ++nf)
#pragma unroll
                for (int c = 0; c < 2; ++c) {
                    int e = nf * 2 + c;
                    float zg = acc[0][nf][c]     + xsv[0][e];
                    float zi = acc[0][nf][2 + c] + xsv[1][e];
                    float zf = acc[1][nf][c]     + xsv[2][e];
                    float zo = acc[1][nf][2 + c] + xsv[3][e];
                    float cv = tanhf(zg) * sigm(zi) + creg[e] * sigm(zf);
                    creg[e] = cv;
                    hv[e] = tanhf(cv) * sigm(zo);
                }
            uint32_t* hw = g_Hp[t & 1];
            const int p2 = gid >> 1;
            const bool even = (gid & 1) == 0;
#pragma unroll
            for (int nf = 0; nf < 4; ++nf)
#pragma unroll
                for (int c = 0; c < 2; ++c) {
                    int e = nf * 2 + c;
                    float partner = __shfl_xor_sync(0xffffffffu, hv[e], 4);
                    if (even) {
                        uint32_t v = h2pack(hv[e], partner);
                        hw[(hk16 * 16 + warp * 4 + nf) * 64 +
                           ((tig * 2 + c) * 4 + p2) * 2 + hreg] = v;
                    }
                }
            if (t == TSTEPS - 1) {
#pragma unroll
                for (int nf = 0; nf < 4; ++nf)
#pragma unroll
                    for (int c = 0; c < 2; ++c)
                        out[(j0 + gid) * BATCH + warp * 32 + nf * 8 + tig * 2 + c] = hv[nf * 2 + c];
            }
        }
        __syncthreads();
        if (tid == 0) { __threadfence(); atomicAdd(&g_bar, 1u); }
    }
}

// ============================================================================
extern "C" void kernel_launch(void* const* d_in, const int* in_sizes, int n_in,
                              void* d_out, int out_size) {
    const float* x   = (const float*)d_in[0];
    const float* c0  = (const float*)d_in[1];
    const float* h0  = (const float*)d_in[2];
    const float* Wgx = (const float*)d_in[3];
    const float* Wix = (const float*)d_in[4];
    const float* Wfx = (const float*)d_in[5];
    const float* Wox = (const float*)d_in[6];
    const float* Wgh = (const float*)d_in[7];
    const float* Wih = (const float*)d_in[8];
    const float* Wfh = (const float*)d_in[9];
    const float* Woh = (const float*)d_in[10];
    const float* bg  = (const float*)d_in[11];
    const float* bi  = (const float*)d_in[12];
    const float* bf  = (const float*)d_in[13];
    const float* bo  = (const float*)d_in[14];
    float* out = (float*)d_out;

    cudaFuncSetAttribute(xproj_kernel, cudaFuncAttributeMaxDynamicSharedMemorySize, 65536);
    cudaFuncSetAttribute(lstm_kernel,  cudaFuncAttributeMaxDynamicSharedMemorySize, 98304);

    prep_w_kernel<<<1024, 256>>>(Wgx, Wix, Wfx, Wox);
    prep_h0_kernel<<<256, 256>>>(h0);
    prep_xt_kernel<<<8192, 256>>>(x);
    xproj_kernel<<<dim3(32, 256), 256, 65536>>>(bg, bi, bf, bo);
    lstm_kernel<<<NB, LT, 98304>>>(c0, Wgh, Wih, Wfh, Woh, out);
}

// round 13
// speedup vs baseline: 1.9358x; 1.0727x over previous
#include <cuda_runtime.h>
#include <cuda_fp16.h>
#include <cstdint>

#define HID    1024
#define INPD   512
#define BATCH  128
#define TSTEPS 256
#define G4H    4096
#define NB     128      // lstm persistent blocks
#define LT     128      // lstm threads (4 warps, all compute)

// ---- device-global scratch (no allocations allowed) ----
__device__ float    g_XS[134217728];          // [t][gate*1024+j][b] fp32 (512 MB)
__device__ uint32_t g_XTh[8388608];           // x fp16 B-frag image (32 MB)
__device__ uint32_t g_WXh[1048576];           // Wx fp16 A-frag image (4 MB)
__device__ uint32_t g_Hp[2][65536];           // h ping-pong, fp16 B-frag-permuted
__device__ unsigned g_flags[NB];              // per-block step flags (grid barrier)

// fp16 m16n8k16, fp32 accum
__device__ __forceinline__ void mma16(float* d, uint32_t a0, uint32_t a1, uint32_t a2,
                                      uint32_t a3, uint32_t b0, uint32_t b1) {
    asm volatile(
        "mma.sync.aligned.m16n8k16.row.col.f32.f16.f16.f32 "
        "{%0,%1,%2,%3}, {%4,%5,%6,%7}, {%8,%9}, {%0,%1,%2,%3};"
        : "+f"(d[0]), "+f"(d[1]), "+f"(d[2]), "+f"(d[3])
        : "r"(a0), "r"(a1), "r"(a2), "r"(a3), "r"(b0), "r"(b1));
}
__device__ __forceinline__ const float* sel4(const float* a, const float* b,
                                             const float* c, const float* d, int g) {
    return g == 0 ? a : (g == 1 ? b : (g == 2 ? c : d));
}
__device__ __forceinline__ float sigm(float x) { return 1.0f / (1.0f + expf(-x)); }
__device__ __forceinline__ uint32_t h2pack(float lo, float hi) {
    __half2 v = __floats2half2_rn(lo, hi);
    return *(uint32_t*)&v;
}
__device__ __forceinline__ void cp16(uint32_t dst, const void* src) {
    asm volatile("cp.async.cg.shared.global [%0], [%1], 16;" :: "r"(dst), "l"(src));
}
__device__ __forceinline__ void cpcommit() { asm volatile("cp.async.commit_group;"); }
template<int N> __device__ __forceinline__ void cpwait() {
    asm volatile("cp.async.wait_group %0;" :: "n"(N));
}

// ============================================================================
// prep_w: Wx concat -> fp16 A-frag image. Resets the flag barrier.
// ============================================================================
__global__ void prep_w_kernel(const float* __restrict__ Wg, const float* __restrict__ Wi,
                              const float* __restrict__ Wf, const float* __restrict__ Wo) {
    if (blockIdx.x == 0 && threadIdx.x < NB) g_flags[threadIdx.x] = 0u;
    int base = blockIdx.x * 256 + threadIdx.x;
#pragma unroll
    for (int i = 0; i < 4; ++i) {
        int o   = base + i * 262144;
        int q   = o & 3, ln = (o >> 2) & 31, k16 = (o >> 7) & 31, mt = o >> 12;
        int R   = mt * 16 + (ln >> 2) + (q & 1) * 8;
        int k   = k16 * 16 + (ln & 3) * 2 + (q >> 1) * 8;
        const float* W = sel4(Wg, Wi, Wf, Wo, R >> 10);
        const float* wr = W + (size_t)(R & 1023) * INPD + k;
        g_WXh[o] = h2pack(wr[0], wr[1]);
    }
}

// ============================================================================
// prep_h0: h0 fp32 [j][b] -> g_Hp[1] fp16 frag-permuted
// ============================================================================
__global__ void prep_h0_kernel(const float* __restrict__ h0) {
    int o = blockIdx.x * 256 + threadIdx.x;          // 65536 u32
    int reg = o & 1, lane = (o >> 1) & 31, n8 = (o >> 6) & 15, k16 = o >> 10;
    int p = lane & 3, gn = lane >> 2;
    int j = k16 * 16 + reg * 8 + 2 * p, b = n8 * 8 + gn;
    g_Hp[1][o] = h2pack(h0[j * BATCH + b], h0[(j + 1) * BATCH + b]);
}

// ============================================================================
// prep_xt: x -> fp16 B-frag image
// ============================================================================
__global__ void prep_xt_kernel(const float* __restrict__ x) {
    int o = blockIdx.x * 1024 + threadIdx.x;
#pragma unroll
    for (int i = 0; i < 4; ++i, o += 256) {
        int reg = o & 1, ln = (o >> 1) & 31, n8 = (o >> 6) & 15, k16 = (o >> 10) & 31, t = o >> 15;
        int p = ln & 3, gn = ln >> 2;
        int ii = k16 * 16 + reg * 8 + 2 * p, b = n8 * 8 + gn;
        const float* xr = x + (size_t)b * (TSTEPS * INPD) + (size_t)t * INPD + ii;
        g_XTh[o] = h2pack(xr[0], xr[1]);
    }
}

// ============================================================================
// xproj (fp16 m16n8k16, unchanged): XS[t][R][b] = Wx[R]·x[b][t] + bias[R]
// ============================================================================
__global__ void __launch_bounds__(256, 2) xproj_kernel(
    const float* __restrict__ bg, const float* __restrict__ bi,
    const float* __restrict__ bf, const float* __restrict__ bo) {
    extern __shared__ uint32_t sm[];
    const uint32_t smem0 = (uint32_t)__cvta_generic_to_shared(sm);
    const int tid = threadIdx.x;
    const int m_base = blockIdx.x * 128;
    const int mt0 = m_base >> 4;
    const int t = blockIdx.y;
    const int warp = tid >> 5, lane = tid & 31;
    const int wm = warp & 1, wn = warp >> 1;
    const int gid = lane >> 2, tig = lane & 3;

    float acc[4][4][4];
#pragma unroll
    for (int a = 0; a < 4; ++a)
#pragma unroll
        for (int b = 0; b < 4; ++b) {
            acc[a][b][0] = acc[a][b][1] = acc[a][b][2] = acc[a][b][3] = 0.f;
        }

    auto issue = [&](int kc, int buf) {
#pragma unroll
        for (int c = 0; c < 4; ++c) {                       // A: 4096 u32
            int u = c * 256 + tid;
            int idx = u >> 5, lq = u & 31;
            int k16l = idx >> 3, mtl = idx & 7;
            const uint32_t* src = g_WXh + ((size_t)(mt0 + mtl) * 32 + kc * 4 + k16l) * 128 + lq * 4;
            cp16(smem0 + (uint32_t)(buf * 4096 + idx * 128 + lq * 4) * 4, src);
        }
#pragma unroll
        for (int c = 0; c < 4; ++c) {                       // B: 4096 u32
            int u = c * 256 + tid;
            int idx = u >> 4, q16 = u & 15;
            const uint32_t* src = g_XTh + ((size_t)(t * 32 + kc * 4) * 16 + idx) * 64 + q16 * 4;
            cp16(smem0 + (uint32_t)(8192 + buf * 4096 + idx * 64 + q16 * 4) * 4, src);
        }
    };
    issue(0, 0); cpcommit();
    issue(1, 1); cpcommit();

#pragma unroll 1
    for (int kc = 0; kc < 8; ++kc) {
        if (kc < 7) cpwait<1>(); else cpwait<0>();
        __syncthreads();
        const uint32_t* A = sm + (kc & 1) * 4096;
        const uint32_t* B = sm + 8192 + (kc & 1) * 4096;
#pragma unroll
        for (int k16l = 0; k16l < 4; ++k16l) {
            uint4 af[4];
#pragma unroll
            for (int mf = 0; mf < 4; ++mf)
                af[mf] = *(const uint4*)(A + ((k16l * 8 + wm * 4 + mf) * 32 + lane) * 4);
#pragma unroll
            for (int nf = 0; nf < 4; ++nf) {
                int n8 = wn * 4 + nf;
                uint2 b01 = *(const uint2*)(B + (k16l * 16 + n8) * 64 + lane * 2);
#pragma unroll
                for (int mf = 0; mf < 4; ++mf)
                    mma16(acc[mf][nf], af[mf].x, af[mf].y, af[mf].z, af[mf].w, b01.x, b01.y);
            }
        }
        __syncthreads();
        if (kc + 2 < 8) { issue(kc + 2, kc & 1); cpcommit(); }
    }

#pragma unroll
    for (int mf = 0; mf < 4; ++mf) {
        int R0 = m_base + wm * 64 + mf * 16 + gid;
        int R1 = R0 + 8;
        float bv0 = sel4(bg, bi, bf, bo, R0 >> 10)[R0 & 1023];
        float bv1 = sel4(bg, bi, bf, bo, R1 >> 10)[R1 & 1023];
#pragma unroll
        for (int nf = 0; nf < 4; ++nf) {
            int cc = wn * 32 + nf * 8 + tig * 2;
            float2 v0 = { acc[mf][nf][0] + bv0, acc[mf][nf][1] + bv0 };
            float2 v1 = { acc[mf][nf][2] + bv1, acc[mf][nf][3] + bv1 };
            *(float2*)&g_XS[((size_t)t * G4H + R0) * BATCH + cc] = v0;
            *(float2*)&g_XS[((size_t)t * G4H + R1) * BATCH + cc] = v1;
        }
    }
}

// ============================================================================
// lstm v7: 128 persistent blocks, 128 threads (4 warps, all compute).
// M=32 (4 gates x 8 units) x N=128 x K=1024, fp16 m16n8k16.
//   - Each warp owns a DISJOINT batch quarter (n8 = warp*4+nf) -> warp-private
//     cp.async B pipeline, NO block syncs in the K-loop (2 per step total).
//   - Flag-array grid barrier (no atomic contention): block stores
//     flag[bid]=t+1; warp 0 polls 128 flags with 4 loads/lane + __all_sync.
//   - register-resident gate epilogue; h written directly to fp16 frag image.
// smem: sW 65536 B + sB 4 x 8192 B = 98304 B.
// ============================================================================
#define SB_OFF   16384                  // u32 offset of sB

__global__ void __launch_bounds__(LT, 1) lstm_kernel(
    const float* __restrict__ c0,
    const float* __restrict__ Wg, const float* __restrict__ Wi,
    const float* __restrict__ Wf, const float* __restrict__ Wo,
    float* __restrict__ out) {
    extern __shared__ uint32_t sm[];
    uint32_t* sW  = sm;                          // 16384 u32 (fp16 A frags)
    const uint32_t smem0 = (uint32_t)__cvta_generic_to_shared(sm);
    const int tid = threadIdx.x;
    const int j0 = blockIdx.x * 8;
    const int warp = tid >> 5, lane = tid & 31;
    const int gid = lane >> 2, tig = lane & 3;
    const int hreg = (j0 >> 3) & 1;
    const int hk16 = j0 >> 4;

    // prologue: Wh -> fp16 A-frag-permuted smem (16384 u32)
#pragma unroll 1
    for (int i = 0; i < 128; ++i) {
        int o    = i * LT + tid;
        int q    = o & 3, ln = (o >> 2) & 31, mt = (o >> 7) & 1, k16 = o >> 8;
        int row  = mt * 16 + (ln >> 2) + (q & 1) * 8;
        int kk   = k16 * 16 + (ln & 3) * 2 + (q >> 1) * 8;
        const float* W = sel4(Wg, Wi, Wf, Wo, row >> 3);
        const float* wr = W + (size_t)(j0 + (row & 7)) * HID + kk;
        sW[o] = h2pack(wr[0], wr[1]);
    }
    // c state in acc layout: creg[nf*2+c] = c(u=gid, n=warp*32+nf*8+tig*2+c)
    float creg[8];
#pragma unroll
    for (int nf = 0; nf < 4; ++nf)
#pragma unroll
        for (int c = 0; c < 2; ++c)
            creg[nf * 2 + c] = c0[(j0 + gid) * BATCH + warp * 32 + nf * 8 + tig * 2 + c];
    __syncthreads();

#pragma unroll 1
    for (int t = 0; t < TSTEPS; ++t) {
        // XS prefetch into registers (independent of barrier -> hides latency)
        float xsv[4][8];
        {
            const size_t xb = (size_t)t * (G4H * BATCH);
            const int nb = warp * 32 + tig * 2;
#pragma unroll
            for (int g = 0; g < 4; ++g) {
                const float* p = &g_XS[xb + (size_t)((g << 10) + j0 + gid) * BATCH + nb];
#pragma unroll
                for (int nf = 0; nf < 4; ++nf) {
                    xsv[g][nf * 2]     = p[nf * 8];
                    xsv[g][nf * 2 + 1] = p[nf * 8 + 1];
                }
            }
        }
        // grid barrier: wait until all blocks finished step t-1
        if (t > 0 && warp == 0) {
            const unsigned tgt = (unsigned)t;
            const volatile unsigned* f = (const volatile unsigned*)g_flags;
            for (;;) {
                unsigned v0 = f[lane], v1 = f[lane + 32], v2 = f[lane + 64], v3 = f[lane + 96];
                bool ok = (v0 >= tgt) && (v1 >= tgt) && (v2 >= tgt) && (v3 >= tgt);
                if (__all_sync(0xffffffffu, ok)) break;
                __nanosleep(32);
            }
            __threadfence();
        }
        __syncthreads();                                  // sync #1

        const uint32_t* hin = g_Hp[(t + 1) & 1];
        // warp-private B pipeline: chunk = 2 k16, this warp's n8 quarter = 512 u32
        auto issueB = [&](int c, int buf) {
#pragma unroll
            for (int i = 0; i < 4; ++i) {
                int rl = i * 2 + (lane >> 4);             // 0..7 = k16l*4 + r
                int col = (lane & 15) * 4;
                int k16l = rl >> 2, r = rl & 3;
                int rowg = (c * 2 + k16l) * 16 + warp * 4 + r;
                int rows = (k16l * 16 + warp * 4 + r);
                cp16(smem0 + (uint32_t)(SB_OFF + buf * 2048 + rows * 64 + col) * 4,
                     hin + (size_t)rowg * 64 + col);
            }
            cpcommit();
        };
        issueB(0, 0); issueB(1, 1); issueB(2, 2);

        float acc[2][4][4];
#pragma unroll
        for (int mt = 0; mt < 2; ++mt)
#pragma unroll
            for (int nf = 0; nf < 4; ++nf) {
                acc[mt][nf][0] = acc[mt][nf][1] = acc[mt][nf][2] = acc[mt][nf][3] = 0.f;
            }
#pragma unroll 1
        for (int kc = 0; kc < 32; ++kc) {
            cpwait<2>();                                  // warp-local wait, no block sync
            const uint32_t* B = sm + SB_OFF + (kc & 3) * 2048;
#pragma unroll
            for (int k16l = 0; k16l < 2; ++k16l) {
                const int k16 = kc * 2 + k16l;
                uint4 a0 = *(const uint4*)(sW + ((k16 * 2) * 32 + lane) * 4);
                uint4 a1 = *(const uint4*)(sW + ((k16 * 2 + 1) * 32 + lane) * 4);
#pragma unroll
                for (int nf = 0; nf < 4; ++nf) {
                    const int n8 = warp * 4 + nf;
                    uint2 b01 = *(const uint2*)(B + (k16l * 16 + n8) * 64 + lane * 2);
                    mma16(acc[0][nf], a0.x, a0.y, a0.z, a0.w, b01.x, b01.y);
                    mma16(acc[1][nf], a1.x, a1.y, a1.z, a1.w, b01.x, b01.y);
                }
            }
            if (kc + 3 < 32) issueB(kc + 3, (kc + 3) & 3);
            else cpcommit();                              // keep group count exact
        }
        // register epilogue + direct h frag write
        {
            float hv[8];
#pragma unroll
            for (int nf = 0; nf < 4; ++nf)
#pragma unroll
                for (int c = 0; c < 2; ++c) {
                    int e = nf * 2 + c;
                    float zg = acc[0][nf][c]     + xsv[0][e];
                    float zi = acc[0][nf][2 + c] + xsv[1][e];
                    float zf = acc[1][nf][c]     + xsv[2][e];
                    float zo = acc[1][nf][2 + c] + xsv[3][e];
                    float cv = tanhf(zg) * sigm(zi) + creg[e] * sigm(zf);
                    creg[e] = cv;
                    hv[e] = tanhf(cv) * sigm(zo);
                }
            uint32_t* hw = g_Hp[t & 1];
            const int p2 = gid >> 1;
            const bool even = (gid & 1) == 0;
#pragma unroll
            for (int nf = 0; nf < 4; ++nf)
#pragma unroll
                for (int c = 0; c < 2; ++c) {
                    int e = nf * 2 + c;
                    float partner = __shfl_xor_sync(0xffffffffu, hv[e], 4);
                    if (even) {
                        uint32_t v = h2pack(hv[e], partner);
                        hw[(hk16 * 16 + warp * 4 + nf) * 64 +
                           ((tig * 2 + c) * 4 + p2) * 2 + hreg] = v;
                    }
                }
            if (t == TSTEPS - 1) {
#pragma unroll
                for (int nf = 0; nf < 4; ++nf)
#pragma unroll
                    for (int c = 0; c < 2; ++c)
                        out[(j0 + gid) * BATCH + warp * 32 + nf * 8 + tig * 2 + c] = hv[nf * 2 + c];
            }
        }
        __threadfence();                                  // each thread releases its h writes
        __syncthreads();                                  // sync #2
        if (tid == 0) *(volatile unsigned*)&g_flags[blockIdx.x] = (unsigned)(t + 1);
    }
}

// ============================================================================
extern "C" void kernel_launch(void* const* d_in, const int* in_sizes, int n_in,
                              void* d_out, int out_size) {
    const float* x   = (const float*)d_in[0];
    const float* c0  = (const float*)d_in[1];
    const float* h0  = (const float*)d_in[2];
    const float* Wgx = (const float*)d_in[3];
    const float* Wix = (const float*)d_in[4];
    const float* Wfx = (const float*)d_in[5];
    const float* Wox = (const float*)d_in[6];
    const float* Wgh = (const float*)d_in[7];
    const float* Wih = (const float*)d_in[8];
    const float* Wfh = (const float*)d_in[9];
    const float* Woh = (const float*)d_in[10];
    const float* bg  = (const float*)d_in[11];
    const float* bi  = (const float*)d_in[12];
    const float* bf  = (const float*)d_in[13];
    const float* bo  = (const float*)d_in[14];
    float* out = (float*)d_out;

    cudaFuncSetAttribute(xproj_kernel, cudaFuncAttributeMaxDynamicSharedMemorySize, 65536);
    cudaFuncSetAttribute(lstm_kernel,  cudaFuncAttributeMaxDynamicSharedMemorySize, 98304);

    prep_w_kernel<<<1024, 256>>>(Wgx, Wix, Wfx, Wox);
    prep_h0_kernel<<<256, 256>>>(h0);
    prep_xt_kernel<<<8192, 256>>>(x);
    xproj_kernel<<<dim3(32, 256), 256, 65536>>>(bg, bi, bf, bo);
    lstm_kernel<<<NB, LT, 98304>>>(c0, Wgh, Wih, Wfh, Woh, out);
}